// round 5
// baseline (speedup 1.0000x reference)
#include <cuda_runtime.h>
#include <stdint.h>

#define NUM_LABELS 100000
#define EMBED      128
#define NTOK       (16 * 4096)

// Scratch: transposed weights, [NUM_LABELS, EMBED] row-major (51.2 MB).
// __device__ global array = allowed scratch (no cudaMalloc).
__device__ float g_Wt[(size_t)NUM_LABELS * EMBED];

// ---------------------------------------------------------------------------
// Kernel 1: transpose W [EMBED, NUM_LABELS] -> g_Wt [NUM_LABELS, EMBED]
//   Tile: 64 labels x 128 embed, staged through SMEM tile[e][l] with +1 pad
//   Loads:  coalesced 128B per warp along the label dimension
//   Writes: coalesced 512B stores along the embed dimension (one Wt row)
//   SMEM: addr = e*65 + l -> bank (e + l) % 32 on both phases: conflict-free
// ---------------------------------------------------------------------------
#define TL 64

__global__ __launch_bounds__(256) void transpose_kernel(const float* __restrict__ W) {
    __shared__ float tile[EMBED][TL + 1];

    const int l0  = blockIdx.x * TL;
    const int tid = threadIdx.x;

    // Load phase: lane -> label, 4 embed rows per thread
    {
        const int l  = tid & (TL - 1);     // 0..63
        const int e0 = tid >> 6;           // 0..3
        const bool valid = (l0 + l) < NUM_LABELS;
        #pragma unroll
        for (int e = e0; e < EMBED; e += 4) {
            tile[e][l] = valid ? W[(size_t)e * NUM_LABELS + (l0 + l)] : 0.0f;
        }
    }
    __syncthreads();

    // Write phase: lane -> embed (conflict-free SMEM reads),
    // 512B coalesced global stores per label row.
    {
        const int e  = tid & (EMBED - 1);  // 0..127
        const int lw = tid >> 7;           // 0..1
        #pragma unroll
        for (int ll = lw; ll < TL; ll += 2) {
            const int lab = l0 + ll;
            if (lab < NUM_LABELS) {
                g_Wt[(size_t)lab * EMBED + e] = tile[e][ll];
            }
        }
    }
}

// ---------------------------------------------------------------------------
// Kernel 2: gather + bias.
//   One warp per token: lane loads float4 of g_Wt[idx] (512B coalesced),
//   adds bias (SMEM-resident), writes float4 to out (512B coalesced).
//   Indices are int32 (JAX downcasts int64 -> int32 without x64 mode;
//   confirmed by the 256KB X allocation faulting under int64 reads).
// ---------------------------------------------------------------------------
__global__ __launch_bounds__(256) void gather_kernel(const int* __restrict__ X,
                                                     const float* __restrict__ bias,
                                                     float* __restrict__ out) {
    __shared__ float4 bs[32];
    const int tid = threadIdx.x;
    if (tid < 32) bs[tid] = reinterpret_cast<const float4*>(bias)[tid];
    __syncthreads();

    const int warp = (blockIdx.x * 256 + tid) >> 5;   // token id (grid exactly covers NTOK)
    const int lane = tid & 31;

    int idx = X[warp];                                // uniform per warp (broadcast load)
    if (idx < 0) idx = 0;
    if (idx >= NUM_LABELS) idx = NUM_LABELS - 1;      // never fault; wrongness shows as rel_err

    const float4* src = reinterpret_cast<const float4*>(g_Wt + (size_t)idx * EMBED);
    float4 v = src[lane];
    const float4 bb = bs[lane];
    v.x += bb.x; v.y += bb.y; v.z += bb.z; v.w += bb.w;

    reinterpret_cast<float4*>(out)[(size_t)warp * 32 + lane] = v;
}

// ---------------------------------------------------------------------------
// Launch. Inputs identified by element count (robust to ordering):
//   65536 -> X (int32 [B,S,1]), 12800000 -> W (f32 [EMBED,NUM_LABELS]), 128 -> b
// Output: float32 [B,S,EMBED]
// ---------------------------------------------------------------------------
extern "C" void kernel_launch(void* const* d_in, const int* in_sizes, int n_in,
                              void* d_out, int out_size) {
    const int*   X = nullptr;
    const float* W = nullptr;
    const float* b = nullptr;

    for (int i = 0; i < n_in; i++) {
        if (in_sizes[i] == NTOK)                    X = (const int*)d_in[i];
        else if (in_sizes[i] == EMBED * NUM_LABELS) W = (const float*)d_in[i];
        else if (in_sizes[i] == EMBED)              b = (const float*)d_in[i];
    }
    // Fallback to positional if size-matching failed
    if (!X) X = (const int*)d_in[0];
    if (!W) W = (const float*)d_in[1];
    if (!b) b = (const float*)d_in[2];

    float* out = (float*)d_out;

    const int tblocks = (NUM_LABELS + TL - 1) / TL;   // 1563
    transpose_kernel<<<tblocks, 256>>>(W);

    const int gblocks = (NTOK * 32) / 256;            // 8192 blocks, 8 tokens each
    gather_kernel<<<gblocks, 256>>>(X, b, out);
}

// round 6
// speedup vs baseline: 1.6213x; 1.6213x over previous
#include <cuda_runtime.h>
#include <stdint.h>

#define NUM_LABELS 100000
#define EMBED      128
#define NTOK       (16 * 4096)

#define BIN_LABELS 64
#define NBINS      ((NUM_LABELS + BIN_LABELS - 1) / BIN_LABELS)   // 1563
#define CAP        1024                                            // slots per bin
#define OVF_CAP    8192

// __device__ scratch (no cudaMalloc): token lists binned by 64-label range.
__device__ int g_cursor[NBINS];        // per-bin atomic cursors
__device__ int g_ovf_cursor;           // overflow cursor
__device__ int g_list[NBINS * CAP];    // packed entries: (token << 6) | local_label
__device__ int g_ovf[OVF_CAP];         // overflow token ids

// ---------------------------------------------------------------------------
// K0: zero the cursors (graph-capturable, no memset API needed)
// ---------------------------------------------------------------------------
__global__ void zero_kernel() {
    int i = blockIdx.x * 256 + threadIdx.x;
    if (i < NBINS) g_cursor[i] = 0;
    if (i == NBINS) g_ovf_cursor = 0;
}

// ---------------------------------------------------------------------------
// K1: bin tokens by label range. entry = (token << 6) | (label % 64).
//     Bin = label >> 6 matches the 64-label tile of K2's blockIdx.
// ---------------------------------------------------------------------------
__global__ __launch_bounds__(256) void bin_kernel(const int* __restrict__ X) {
    int t = blockIdx.x * 256 + threadIdx.x;         // token id, grid covers NTOK exactly
    int idx = X[t];
    if (idx < 0) idx = 0;
    if (idx >= NUM_LABELS) idx = NUM_LABELS - 1;    // never fault

    int bin = idx >> 6;
    int pos = atomicAdd(&g_cursor[bin], 1);
    if (pos < CAP) {
        g_list[bin * CAP + pos] = (t << 6) | (idx & 63);
    } else {
        int p = atomicAdd(&g_ovf_cursor, 1);
        if (p < OVF_CAP) g_ovf[p] = t;
    }
}

// ---------------------------------------------------------------------------
// K2: fused transpose + scatter + bias.
//   Block b: load W[:, b*64 .. b*64+63] into SMEM tile[lab][e] (pitch 129 =>
//   bank (lab+e)%32, conflict-free both phases), then for each token in bin b
//   write out[token][:] = tile[local_lab][:] + bias.
//   Global loads: 128B coalesced per warp. Global stores: 128B coalesced per
//   warp, 512B contiguous per token (full lines, no RFO).
// ---------------------------------------------------------------------------
__global__ __launch_bounds__(256) void fused_kernel(const float* __restrict__ W,
                                                    const float* __restrict__ bias,
                                                    float* __restrict__ out) {
    __shared__ float tile[BIN_LABELS][EMBED + 1];   // 33 KB, conflict-free
    __shared__ float bs[EMBED];
    __shared__ int   entries[256];

    const int bin = blockIdx.x;
    const int l0  = bin << 6;
    const int tid = threadIdx.x;

    if (tid < EMBED) bs[tid] = bias[tid];

    // Tile load: lane -> label (coalesced 128B/warp), 32 e-rows per thread.
    {
        const int l  = tid & (BIN_LABELS - 1);      // 0..63
        const int e0 = tid >> 6;                    // 0..3
        const bool valid = (l0 + l) < NUM_LABELS;
        #pragma unroll
        for (int e = e0; e < EMBED; e += 4) {
            tile[l][e] = valid ? W[(size_t)e * NUM_LABELS + (l0 + l)] : 0.0f;
        }
    }

    int count = g_cursor[bin];
    if (count > CAP) count = CAP;

    const int warp = tid >> 5;
    const int lane = tid & 31;

    for (int base = 0; base < count; base += 256) {
        const int n = min(256, count - base);
        __syncthreads();                            // tile ready / entries reusable
        if (tid < n) entries[tid] = g_list[bin * CAP + base + tid];
        __syncthreads();

        for (int i = warp; i < n; i += 8) {         // one warp per token
            const int ent = entries[i];
            const int tok = ent >> 6;
            const int lab = ent & 63;
            float* o = out + (size_t)tok * EMBED;
            #pragma unroll
            for (int k = 0; k < 4; k++) {
                const int e = lane + 32 * k;        // bank (lab+lane)%32: conflict-free
                o[e] = tile[lab][e] + bs[e];
            }
        }
    }
}

// ---------------------------------------------------------------------------
// K3: overflow fixup (correctness guarantee; normally zero work).
//   One block per overflow token round; 128 threads = 128 embed dims,
//   strided W reads (slow path, count ~ 0).
// ---------------------------------------------------------------------------
__global__ __launch_bounds__(128) void overflow_kernel(const int* __restrict__ X,
                                                       const float* __restrict__ W,
                                                       const float* __restrict__ bias,
                                                       float* __restrict__ out) {
    int n = g_ovf_cursor;
    if (n > OVF_CAP) n = OVF_CAP;
    const int e = threadIdx.x;
    for (int i = blockIdx.x; i < n; i += gridDim.x) {
        const int tok = g_ovf[i];
        int idx = X[tok];
        if (idx < 0) idx = 0;
        if (idx >= NUM_LABELS) idx = NUM_LABELS - 1;
        out[(size_t)tok * EMBED + e] = W[(size_t)e * NUM_LABELS + idx] + bias[e];
    }
}

// ---------------------------------------------------------------------------
// Launch. Inputs identified by element count (robust to ordering):
//   65536 -> X (int32), 12800000 -> W (f32 [EMBED,NUM_LABELS]), 128 -> b
// ---------------------------------------------------------------------------
extern "C" void kernel_launch(void* const* d_in, const int* in_sizes, int n_in,
                              void* d_out, int out_size) {
    const int*   X = nullptr;
    const float* W = nullptr;
    const float* b = nullptr;

    for (int i = 0; i < n_in; i++) {
        if (in_sizes[i] == NTOK)                    X = (const int*)d_in[i];
        else if (in_sizes[i] == EMBED * NUM_LABELS) W = (const float*)d_in[i];
        else if (in_sizes[i] == EMBED)              b = (const float*)d_in[i];
    }
    if (!X) X = (const int*)d_in[0];
    if (!W) W = (const float*)d_in[1];
    if (!b) b = (const float*)d_in[2];

    float* out = (float*)d_out;

    zero_kernel<<<(NBINS + 256) / 256, 256>>>();
    bin_kernel<<<NTOK / 256, 256>>>(X);
    fused_kernel<<<NBINS, 256>>>(W, b, out);
    overflow_kernel<<<16, 128>>>(X, W, b, out);
}